// round 4
// baseline (speedup 1.0000x reference)
#include <cuda_runtime.h>
#include <math.h>

// Skipgram negative-sampling loss — single fused kernel, MLP-widened gather.
// Inputs (metadata order):
//   d_in[0] center_id       int32 [B]
//   d_in[1] pos_context_id  int32 [B]
//   d_in[2] neg_context_ids int32 [B, K]
//   d_in[3] W_in            f32   [VOCAB, DIM]
//   d_in[4] W_out           f32   [VOCAB, DIM]
// Output: scalar f32 = -(sum log_sigmoid(pos_score) + sum log_sigmoid(-neg_score))

#define BATCH 16384
#define KNEG  10
#define DIMV4 32          // 128 floats = 32 float4 per row
#define NBLK  2048        // BATCH / 8 warps per block

__device__ float g_partial[NBLK];
__device__ unsigned int g_count = 0;   // reset by last block each call (graph-replay safe)

__device__ __forceinline__ float log_sigmoid(float x) {
    // stable: min(x,0) - log1p(exp(-|x|))
    return fminf(x, 0.0f) - log1pf(__expf(-fabsf(x)));
}

__global__ __launch_bounds__(256, 3) void skipgram_fused(
    const int* __restrict__ center_id,
    const int* __restrict__ pos_id,
    const int* __restrict__ neg_ids,
    const float4* __restrict__ Win,
    const float4* __restrict__ Wout,
    float* __restrict__ out)
{
    const int lane = threadIdx.x & 31;
    const int warp_in_blk = threadIdx.x >> 5;
    const int b = blockIdx.x * 8 + warp_in_blk;   // one warp per batch element

    // ---- Index phase: everything needed to form all 12 row addresses ----
    const int cid = center_id[b];
    const int pid = pos_id[b];
    int my_nid = 0;
    if (lane < KNEG) my_nid = neg_ids[b * KNEG + lane];

    int nid[KNEG];
#pragma unroll
    for (int k = 0; k < KNEG; ++k)
        nid[k] = __shfl_sync(0xffffffffu, my_nid, k);

    // ---- Load phase: issue all 12 independent LDG.128s back-to-back ----
    const float4 c = Win [(size_t)cid * DIMV4 + lane];
    const float4 p = Wout[(size_t)pid * DIMV4 + lane];
    float4 v[KNEG];
#pragma unroll
    for (int k = 0; k < KNEG; ++k)
        v[k] = Wout[(size_t)nid[k] * DIMV4 + lane];

    // ---- Reduce phase ----
    // Two independent accumulator chains to shorten the FADD dependency.
    float4 na = make_float4(0.f, 0.f, 0.f, 0.f);
    float4 nb = make_float4(0.f, 0.f, 0.f, 0.f);
#pragma unroll
    for (int k = 0; k < KNEG; k += 2) {
        na.x += v[k].x;   na.y += v[k].y;   na.z += v[k].z;   na.w += v[k].w;
        nb.x += v[k+1].x; nb.y += v[k+1].y; nb.z += v[k+1].z; nb.w += v[k+1].w;
    }
    const float4 nsum = make_float4(na.x + nb.x, na.y + nb.y, na.z + nb.z, na.w + nb.w);

    float pd = c.x * p.x + c.y * p.y + c.z * p.z + c.w * p.w;
    float nd = c.x * nsum.x + c.y * nsum.y + c.z * nsum.z + c.w * nsum.w;

#pragma unroll
    for (int o = 16; o > 0; o >>= 1) {
        pd += __shfl_xor_sync(0xffffffffu, pd, o);
        nd += __shfl_xor_sync(0xffffffffu, nd, o);
    }

    __shared__ float s[8];
    __shared__ bool is_last;
    if (lane == 0)
        s[warp_in_blk] = log_sigmoid(pd) + log_sigmoid(-nd);
    __syncthreads();

    if (threadIdx.x == 0) {
        float t = 0.f;
#pragma unroll
        for (int i = 0; i < 8; ++i) t += s[i];
        g_partial[blockIdx.x] = t;
        __threadfence();
        unsigned int old = atomicAdd(&g_count, 1u);
        is_last = (old == NBLK - 1);
    }
    __syncthreads();

    if (is_last) {
        // Last block: deterministic fixed-order reduction of all partials.
        float t = 0.f;
#pragma unroll
        for (int i = 0; i < NBLK / 256; ++i)
            t += g_partial[threadIdx.x + i * 256];   // 8 loads per thread, fixed order

#pragma unroll
        for (int o = 16; o > 0; o >>= 1)
            t += __shfl_xor_sync(0xffffffffu, t, o);

        __shared__ float s2[8];
        if (lane == 0) s2[warp_in_blk] = t;
        __syncthreads();

        if (threadIdx.x == 0) {
            float tot = 0.f;
#pragma unroll
            for (int i = 0; i < 8; ++i) tot += s2[i];
            out[0] = -tot;
            g_count = 0;   // reset for next graph replay
        }
    }
}

extern "C" void kernel_launch(void* const* d_in, const int* in_sizes, int n_in,
                              void* d_out, int out_size)
{
    const int*    center_id = (const int*)   d_in[0];
    const int*    pos_id    = (const int*)   d_in[1];
    const int*    neg_ids   = (const int*)   d_in[2];
    const float4* Win       = (const float4*)d_in[3];
    const float4* Wout      = (const float4*)d_in[4];
    float* out = (float*)d_out;

    skipgram_fused<<<NBLK, 256>>>(center_id, pos_id, neg_ids, Win, Wout, out);
}

// round 5
// speedup vs baseline: 1.0905x; 1.0905x over previous
#include <cuda_runtime.h>
#include <math.h>

// Skipgram negative-sampling loss — fused kernel, cp.async-gathered negatives.
// Inputs (metadata order):
//   d_in[0] center_id       int32 [B]
//   d_in[1] pos_context_id  int32 [B]
//   d_in[2] neg_context_ids int32 [B, K]
//   d_in[3] W_in            f32   [VOCAB, DIM]
//   d_in[4] W_out           f32   [VOCAB, DIM]
// Output: scalar f32 = -(sum log_sigmoid(pos_score) + sum log_sigmoid(-neg_score))

#define BATCH 16384
#define KNEG  10
#define DIMV4 32          // 128 floats = 32 float4 per row
#define WPB   8           // warps per block
#define NBLK  2048        // BATCH / WPB

__device__ float g_partial[NBLK];
__device__ unsigned int g_count = 0;   // reset by last block each call (graph-replay safe)

__device__ __forceinline__ float log_sigmoid(float x) {
    return fminf(x, 0.0f) - log1pf(__expf(-fabsf(x)));
}

__device__ __forceinline__ void cp_async16(void* smem_dst, const void* gmem_src) {
    unsigned int s = (unsigned int)__cvta_generic_to_shared(smem_dst);
    asm volatile("cp.async.cg.shared.global [%0], [%1], 16;\n" :: "r"(s), "l"(gmem_src));
}

__global__ __launch_bounds__(256) void skipgram_fused(
    const int* __restrict__ center_id,
    const int* __restrict__ pos_id,
    const int* __restrict__ neg_ids,
    const float4* __restrict__ Win,
    const float4* __restrict__ Wout,
    float* __restrict__ out)
{
    // Staging buffer: 10 neg rows per warp, lane-sliced. 8*10*32*16B = 40KB.
    __shared__ float4 buf[WPB][KNEG][32];

    const int lane = threadIdx.x & 31;
    const int w    = threadIdx.x >> 5;
    const int b    = blockIdx.x * WPB + w;   // one warp per batch element

    // ---- Indices ----
    const int cid = center_id[b];
    const int pid = pos_id[b];
    int my_nid = 0;
    if (lane < KNEG) my_nid = neg_ids[b * KNEG + lane];

    // ---- Direct loads for center/pos (2 regs of MLP) ----
    const float4 c = Win [(size_t)cid * DIMV4 + lane];
    const float4 p = Wout[(size_t)pid * DIMV4 + lane];

    // ---- Async gather of all 10 negative rows: MLP without registers ----
#pragma unroll
    for (int k = 0; k < KNEG; ++k) {
        const int id = __shfl_sync(0xffffffffu, my_nid, k);
        cp_async16(&buf[w][k][lane], Wout + (size_t)id * DIMV4 + lane);
    }
    asm volatile("cp.async.commit_group;\n" ::: "memory");
    asm volatile("cp.async.wait_group 0;\n" ::: "memory");
    __syncwarp();

    // ---- Reduce: two accumulator chains over smem rows ----
    float4 na = make_float4(0.f, 0.f, 0.f, 0.f);
    float4 nb = make_float4(0.f, 0.f, 0.f, 0.f);
#pragma unroll
    for (int k = 0; k < KNEG; k += 2) {
        const float4 va = buf[w][k][lane];
        const float4 vb = buf[w][k + 1][lane];
        na.x += va.x; na.y += va.y; na.z += va.z; na.w += va.w;
        nb.x += vb.x; nb.y += vb.y; nb.z += vb.z; nb.w += vb.w;
    }
    const float4 nsum = make_float4(na.x + nb.x, na.y + nb.y, na.z + nb.z, na.w + nb.w);

    float pd = c.x * p.x + c.y * p.y + c.z * p.z + c.w * p.w;
    float nd = c.x * nsum.x + c.y * nsum.y + c.z * nsum.z + c.w * nsum.w;

#pragma unroll
    for (int o = 16; o > 0; o >>= 1) {
        pd += __shfl_xor_sync(0xffffffffu, pd, o);
        nd += __shfl_xor_sync(0xffffffffu, nd, o);
    }

    __shared__ float s[WPB];
    __shared__ bool is_last;
    if (lane == 0)
        s[w] = log_sigmoid(pd) + log_sigmoid(-nd);
    __syncthreads();

    if (threadIdx.x == 0) {
        float t = 0.f;
#pragma unroll
        for (int i = 0; i < WPB; ++i) t += s[i];
        g_partial[blockIdx.x] = t;
        __threadfence();
        unsigned int old = atomicAdd(&g_count, 1u);
        is_last = (old == NBLK - 1);
    }
    __syncthreads();

    if (is_last) {
        // Deterministic fixed-order reduction of all partials.
        float t = 0.f;
#pragma unroll
        for (int i = 0; i < NBLK / 256; ++i)
            t += g_partial[threadIdx.x + i * 256];

#pragma unroll
        for (int o = 16; o > 0; o >>= 1)
            t += __shfl_xor_sync(0xffffffffu, t, o);

        __shared__ float s2[WPB];
        if (lane == 0) s2[w] = t;
        __syncthreads();

        if (threadIdx.x == 0) {
            float tot = 0.f;
#pragma unroll
            for (int i = 0; i < WPB; ++i) tot += s2[i];
            out[0] = -tot;
            g_count = 0;   // reset for next graph replay
        }
    }
}

extern "C" void kernel_launch(void* const* d_in, const int* in_sizes, int n_in,
                              void* d_out, int out_size)
{
    const int*    center_id = (const int*)   d_in[0];
    const int*    pos_id    = (const int*)   d_in[1];
    const int*    neg_ids   = (const int*)   d_in[2];
    const float4* Win       = (const float4*)d_in[3];
    const float4* Wout      = (const float4*)d_in[4];
    float* out = (float*)d_out;

    skipgram_fused<<<NBLK, 256>>>(center_id, pos_id, neg_ids, Win, Wout, out);
}